// round 14
// baseline (speedup 1.0000x reference)
#include <cuda_runtime.h>
#include <math_constants.h>
#include <cstdint>

#define BSZ   2
#define TSEQ  2048
#define CDIM  1024
#define HN    16
#define DH    64

// Scratch (allocation-free rule: __device__ globals)
__device__ float g_Q[(size_t)BSZ*HN*TSEQ*DH];   // [B,H,T,D]
__device__ float g_K[(size_t)BSZ*HN*TSEQ*DH];
__device__ float g_V[(size_t)BSZ*HN*TSEQ*DH];
__device__ float g_att[(size_t)BSZ*TSEQ*CDIM];  // [B,T,C] (tf32-rounded)
__device__ float g_xc[(size_t)BSZ*TSEQ*CDIM];   // x pre-rounded to tf32
__device__ float g_Wc[4][(size_t)CDIM*CDIM];    // Wq,Wk,Wv,Wo pre-rounded

// packed bf16x2 buffers (produced once per call by pack_kernel)
#define NWORD_QK ((size_t)BSZ*HN*TSEQ*(DH/2))
__device__ uint32_t g_Qh[NWORD_QK], g_Ql[NWORD_QK];      // [bh][t][d/2], qscale folded
// word-interleaved hi/lo: [bh][t][2*(d/2)] = ...,hi_p,lo_p,...
__device__ uint32_t g_Kc[(size_t)BSZ*HN*TSEQ*DH];
// V transposed + interleaved: [bh][d][2*(t/2)] = ...,hi_p,lo_p,...
__device__ uint32_t g_Vc[(size_t)BSZ*HN*DH*TSEQ];

// ---------------------------------------------------------------------------
// helpers
// ---------------------------------------------------------------------------
__device__ __forceinline__ uint32_t smem_u32(const void* p) {
    uint32_t a;
    asm("{ .reg .u64 t; cvta.to.shared.u64 t, %1; cvt.u32.u64 %0, t; }"
        : "=r"(a) : "l"(p));
    return a;
}

__device__ __forceinline__ float fast_exp2(float x) {
    float y;
    asm("ex2.approx.f32 %0, %1;" : "=f"(y) : "f"(x));
    return y;
}

__device__ __forceinline__ float to_tf32(float x) {
    float r;
    asm("cvt.rna.tf32.f32 %0, %1;" : "=f"(r) : "f"(x));
    return r;
}

__device__ __forceinline__ void cp_async16(uint32_t dst, const void* src) {
    asm volatile("cp.async.cg.shared.global [%0], [%1], 16;" :: "r"(dst), "l"(src));
}
__device__ __forceinline__ void cp_commit() {
    asm volatile("cp.async.commit_group;");
}
template <int N>
__device__ __forceinline__ void cp_wait() {
    asm volatile("cp.async.wait_group %0;" :: "n"(N));
}

// pack two f32 into bf16x2: low half <- lo, high half <- hi
__device__ __forceinline__ uint32_t pack_bf16x2(float lo, float hi) {
    uint32_t r;
    asm("cvt.rn.bf16x2.f32 %0, %1, %2;" : "=r"(r) : "f"(hi), "f"(lo));
    return r;
}
__device__ __forceinline__ float bf16lo_f(uint32_t w) { return __uint_as_float(w << 16); }
__device__ __forceinline__ float bf16hi_f(uint32_t w) { return __uint_as_float(w & 0xFFFF0000u); }

// tf32 mma.sync m16n8k8 (non-volatile: pure computation)
__device__ __forceinline__ void mma_tf32(float* d, const uint32_t* a, const uint32_t* b)
{
    asm("mma.sync.aligned.m16n8k8.row.col.f32.tf32.tf32.f32 "
        "{%0,%1,%2,%3}, {%4,%5,%6,%7}, {%8,%9}, {%0,%1,%2,%3};"
        : "+f"(d[0]), "+f"(d[1]), "+f"(d[2]), "+f"(d[3])
        : "r"(a[0]), "r"(a[1]), "r"(a[2]), "r"(a[3]),
          "r"(b[0]), "r"(b[1]));
}

// bf16 mma.sync m16n8k16 (non-volatile)
__device__ __forceinline__ void mma_bf16(float* d, const uint32_t* a, uint32_t b0, uint32_t b1)
{
    asm("mma.sync.aligned.m16n8k16.row.col.f32.bf16.bf16.f32 "
        "{%0,%1,%2,%3}, {%4,%5,%6,%7}, {%8,%9}, {%0,%1,%2,%3};"
        : "+f"(d[0]), "+f"(d[1]), "+f"(d[2]), "+f"(d[3])
        : "r"(a[0]), "r"(a[1]), "r"(a[2]), "r"(a[3]),
          "r"(b0), "r"(b1));
}

// ---------------------------------------------------------------------------
// tf32 pre-conversion pass: x + 4 weight matrices, RNA-rounded once per call.
// ---------------------------------------------------------------------------
__global__ __launch_bounds__(256)
void cvt_tf32_kernel(const float* __restrict__ x,
                     const float* __restrict__ Wq, const float* __restrict__ Wk,
                     const float* __restrict__ Wv, const float* __restrict__ Wo)
{
    const int y = blockIdx.y;
    const float* src;
    float* dst;
    int n4;
    if (y == 0)      { src = x;  dst = g_xc;    n4 = BSZ * TSEQ * CDIM / 4; }
    else if (y == 1) { src = Wq; dst = g_Wc[0]; n4 = CDIM * CDIM / 4; }
    else if (y == 2) { src = Wk; dst = g_Wc[1]; n4 = CDIM * CDIM / 4; }
    else if (y == 3) { src = Wv; dst = g_Wc[2]; n4 = CDIM * CDIM / 4; }
    else             { src = Wo; dst = g_Wc[3]; n4 = CDIM * CDIM / 4; }

    const int i = blockIdx.x * blockDim.x + threadIdx.x;
    if (i < n4) {
        float4 v = ((const float4*)src)[i];
        v.x = to_tf32(v.x); v.y = to_tf32(v.y);
        v.z = to_tf32(v.z); v.w = to_tf32(v.w);
        ((float4*)dst)[i] = v;
    }
}

// ---------------------------------------------------------------------------
// Pack pass: bf16 hi/lo split of Q (qscale folded), K (interleaved), and
// transposed V (interleaved). Grid (T/64, B*H), 256 threads.
// ---------------------------------------------------------------------------
__global__ __launch_bounds__(256)
void pack_kernel()
{
    __shared__ float sv[64][68];   // V tile [t][d]

    const int bh = blockIdx.y;
    const int t0 = blockIdx.x * 64;
    const int tid = threadIdx.x;
    const float qscale = 0.125f * 1.4426950408889634f;   // 1/sqrt(D)*log2(e)

    // load V tile [t0..t0+63][0..63]
#pragma unroll
    for (int i = 0; i < 4; ++i) {
        const int idx = tid + i * 256;
        const int row = idx >> 4;
        const int c4  = (idx & 15) * 4;
        *(float4*)&sv[row][c4] =
            *(const float4*)&g_V[((size_t)bh * TSEQ + t0 + row) * DH + c4];
    }

    // Q (separate hi/lo) and K (word-interleaved hi/lo)
#pragma unroll
    for (int i = 0; i < 8; ++i) {
        const int idx = tid + i * 256;        // (row, pair)
        const int row = idx >> 5;
        const int p   = idx & 31;
        const size_t src = ((size_t)bh * TSEQ + t0 + row) * DH + 2 * p;
        const size_t dstq = ((size_t)bh * TSEQ + t0 + row) * (DH / 2) + p;

        float2 q = *(const float2*)&g_Q[src];
        q.x *= qscale; q.y *= qscale;
        uint32_t qh = pack_bf16x2(q.x, q.y);
        g_Qh[dstq] = qh;
        g_Ql[dstq] = pack_bf16x2(q.x - bf16lo_f(qh), q.y - bf16hi_f(qh));

        float2 k = *(const float2*)&g_K[src];
        uint32_t kh = pack_bf16x2(k.x, k.y);
        uint32_t kl = pack_bf16x2(k.x - bf16lo_f(kh), k.y - bf16hi_f(kh));
        uint2 kw; kw.x = kh; kw.y = kl;
        *(uint2*)&g_Kc[((size_t)bh * TSEQ + t0 + row) * DH + 2 * p] = kw;
    }
    __syncthreads();

    // V transposed + interleaved: words (hi,lo) at [bh][d][t0 + 2p]
#pragma unroll
    for (int i = 0; i < 8; ++i) {
        const int idx = tid + i * 256;        // (d, pair)
        const int d = idx >> 5;
        const int p = idx & 31;
        const float v0 = sv[2 * p][d];
        const float v1 = sv[2 * p + 1][d];
        const uint32_t h = pack_bf16x2(v0, v1);
        uint2 vw;
        vw.x = h;
        vw.y = pack_bf16x2(v0 - bf16lo_f(h), v1 - bf16hi_f(h));
        *(uint2*)&g_Vc[((size_t)bh * DH + d) * TSEQ + t0 + 2 * p] = vw;
    }
}

// ---------------------------------------------------------------------------
// tf32 tensor-core GEMM-NT, cp.async double-buffered, 2 CTAs/SM (proven).
// ---------------------------------------------------------------------------
#define GPAD 36
#define GEMM_SMEM (4 * 128 * GPAD * 4)   // 73728 B

template <int MODE, int NMAT>
__global__ __launch_bounds__(256, 2)
void gemm_mma_kernel(const float* __restrict__ A,
                     const float* __restrict__ W0, const float* __restrict__ W1,
                     const float* __restrict__ W2,
                     const float* __restrict__ b0, const float* __restrict__ b1,
                     const float* __restrict__ b2,
                     float* __restrict__ o0, float* __restrict__ o1,
                     float* __restrict__ o2)
{
    extern __shared__ float smem[];
    float (*As)[128][GPAD] = (float (*)[128][GPAD])(smem);
    float (*Bs)[128][GPAD] = (float (*)[128][GPAD])(smem + 2 * 128 * GPAD);
    const uint32_t smem_base = smem_u32(smem);

    const int z = (NMAT == 3) ? (int)blockIdx.z : 0;
    const float* __restrict__ W    = (z == 0) ? W0 : (z == 1 ? W1 : W2);
    const float* __restrict__ bias = (z == 0) ? b0 : (z == 1 ? b1 : b2);
    float* __restrict__ out        = (z == 0) ? o0 : (z == 1 ? o1 : o2);

    const int tid  = threadIdx.x;
    const int wid  = tid >> 5;
    const int lane = tid & 31;
    const int gID  = lane >> 2;
    const int tig  = lane & 3;
    const int n0 = blockIdx.x * 128;
    const int m0 = blockIdx.y * 128;
    const int wm = (wid >> 2) * 64;
    const int wn = (wid & 3) * 32;

    float acc[4][4][4];
#pragma unroll
    for (int mt = 0; mt < 4; ++mt)
#pragma unroll
        for (int nt = 0; nt < 4; ++nt)
#pragma unroll
            for (int r = 0; r < 4; ++r) acc[mt][nt][r] = 0.f;

    auto issue = [&](int buf, int k0) {
#pragma unroll
        for (int i = 0; i < 4; ++i) {
            const int idx = tid + i * 256;
            const int row = idx >> 3;
            const int q4  = (idx & 7) * 4;
            const uint32_t dA = smem_base +
                4u * (uint32_t)((buf * 128 + row) * GPAD + q4);
            const uint32_t dB = smem_base +
                4u * (uint32_t)(2 * 128 * GPAD + (buf * 128 + row) * GPAD + q4);
            cp_async16(dA, A + (size_t)(m0 + row) * CDIM + k0 + q4);
            cp_async16(dB, W + (size_t)(n0 + row) * CDIM + k0 + q4);
        }
        cp_commit();
    };

    issue(0, 0);

    for (int c = 0; c < 32; ++c) {
        const int cur = c & 1;
        if (c + 1 < 32) {
            issue(cur ^ 1, (c + 1) * 32);
            cp_wait<1>();
        } else {
            cp_wait<0>();
        }
        __syncthreads();

#pragma unroll
        for (int ks = 0; ks < 4; ++ks) {
            const int kk = ks * 8;
            uint32_t af[4][4];
#pragma unroll
            for (int mt = 0; mt < 4; ++mt) {
                const int r0 = wm + mt * 16 + gID;
                af[mt][0] = __float_as_uint(As[cur][r0    ][kk + tig    ]);
                af[mt][1] = __float_as_uint(As[cur][r0 + 8][kk + tig    ]);
                af[mt][2] = __float_as_uint(As[cur][r0    ][kk + tig + 4]);
                af[mt][3] = __float_as_uint(As[cur][r0 + 8][kk + tig + 4]);
            }
            uint32_t bf[4][2];
#pragma unroll
            for (int nt = 0; nt < 4; ++nt) {
                const int rn = wn + nt * 8 + gID;
                bf[nt][0] = __float_as_uint(Bs[cur][rn][kk + tig    ]);
                bf[nt][1] = __float_as_uint(Bs[cur][rn][kk + tig + 4]);
            }
#pragma unroll
            for (int mt = 0; mt < 4; ++mt)
#pragma unroll
                for (int nt = 0; nt < 4; ++nt)
                    mma_tf32(acc[mt][nt], af[mt], bf[nt]);
        }
        __syncthreads();
    }

#pragma unroll
    for (int mt = 0; mt < 4; ++mt) {
#pragma unroll
        for (int nt = 0; nt < 4; ++nt) {
            const int mrow0 = m0 + wm + mt * 16 + gID;
            const int mrow1 = mrow0 + 8;
            const int ncol  = n0 + wn + nt * 8 + 2 * tig;
            const float bx = bias[ncol], by = bias[ncol + 1];
            float2 v0, v1;
            v0.x = acc[mt][nt][0] + bx; v0.y = acc[mt][nt][1] + by;
            v1.x = acc[mt][nt][2] + bx; v1.y = acc[mt][nt][3] + by;
            if (MODE == 0) {
                *(float2*)&out[(size_t)mrow0 * CDIM + ncol] = v0;
                *(float2*)&out[(size_t)mrow1 * CDIM + ncol] = v1;
            } else {
                const int h  = ncol >> 6;
                const int dd = ncol & 63;
                const int b0r = mrow0 >> 11, t0r = mrow0 & (TSEQ - 1);
                const int b1r = mrow1 >> 11, t1r = mrow1 & (TSEQ - 1);
                *(float2*)&out[(((size_t)(b0r * HN + h)) * TSEQ + t0r) * DH + dd] = v0;
                *(float2*)&out[(((size_t)(b1r * HN + h)) * TSEQ + t1r) * DH + dd] = v1;
            }
        }
    }
}

// ----------------------------------------------------------------------------
// Tensor-core causal flash attention (bf16 split-3, ~fp32 accurate).
// hi/lo word-interleaved K/V => B-fragment pairs load as single LDS.64.
// Row pitch 72 words: LDS.64 banks (8*gID+2*tig) conflict-free per half-warp.
// Double-buffered cp.async staging; l-reduction deferred to epilogue.
// Block: 128 threads (4 warps). Q-tile 64, KV-tile 64. Grid: (T/64, B*H).
// ----------------------------------------------------------------------------
#define KP2 72
#define AWORDS (64 * KP2)                        // 4608 words per array
#define FLASH_SMEM (2 * 2 * AWORDS * 4)          // 2 bufs x (K + V) = 73728 B

__global__ __launch_bounds__(128)
void flash_attn_mma_kernel(float* __restrict__ att)
{
    extern __shared__ uint32_t fsm[];
    // layout: [buf][K, V][AWORDS]
    const uint32_t fsm_base = smem_u32(fsm);

    const int bh  = blockIdx.y;
    const int bx  = gridDim.x - 1 - blockIdx.x;
    const int q0  = bx * 64;
    const int tid = threadIdx.x;
    const int wid = tid >> 5;
    const int lane = tid & 31;
    const int gID = lane >> 2;
    const int tig = lane & 3;

    const int rA = q0 + wid * 16 + gID;
    const int rB = rA + 8;

    // ---- Q fragments from packed buffers (qscale already folded)
    uint32_t qhi[4][4], qlo[4][4];
    {
        const uint32_t* QhA = g_Qh + ((size_t)bh * TSEQ + rA) * (DH / 2);
        const uint32_t* QhB = g_Qh + ((size_t)bh * TSEQ + rB) * (DH / 2);
        const uint32_t* QlA = g_Ql + ((size_t)bh * TSEQ + rA) * (DH / 2);
        const uint32_t* QlB = g_Ql + ((size_t)bh * TSEQ + rB) * (DH / 2);
#pragma unroll
        for (int ks = 0; ks < 4; ++ks) {
            const int p = 8 * ks + tig;
            qhi[ks][0] = QhA[p];     qhi[ks][1] = QhB[p];
            qhi[ks][2] = QhA[p + 4]; qhi[ks][3] = QhB[p + 4];
            qlo[ks][0] = QlA[p];     qlo[ks][1] = QlB[p];
            qlo[ks][2] = QlA[p + 4]; qlo[ks][3] = QlB[p + 4];
        }
    }

    // issue cp.async staging of KV tile `kbase` into buffer `buf`.
    // Each row: 64 payload words (32 pairs interleaved hi/lo) + 8 pad.
    auto stage = [&](int buf, int kbase) {
        const uint32_t kb = fsm_base + 4u * (uint32_t)(buf * 2 * AWORDS);
        const uint32_t vb = kb + 4u * (uint32_t)AWORDS;
#pragma unroll
        for (int i = 0; i < 8; ++i) {
            const int idx = tid + i * 128;      // 0..1023
            const int row = idx >> 4;           // 0..63 (key for K, d for V)
            const int c   = idx & 15;           // 16B chunk within 256B payload
            const uint32_t off = 4u * (uint32_t)(row * KP2 + c * 4);
            cp_async16(kb + off,
                       g_Kc + ((size_t)bh * TSEQ + kbase + row) * DH + c * 4);
            cp_async16(vb + off,
                       g_Vc + ((size_t)bh * DH + row) * TSEQ + kbase + c * 4);
        }
        cp_commit();
    };

    float O[8][4];
#pragma unroll
    for (int nt = 0; nt < 8; ++nt)
#pragma unroll
        for (int r = 0; r < 4; ++r) O[nt][r] = 0.f;
    float mA = -1e30f, mB = -1e30f, lA = 0.f, lB = 0.f;   // l: per-thread partial

    const int ntiles = bx + 1;

    stage(0, 0);

    for (int kt = 0; kt < ntiles; ++kt) {
        const int cur = kt & 1;
        const int kbase = kt * 64;

        __syncthreads();                  // all warps done with buffer cur (prev use)
        if (kt + 1 < ntiles) {
            stage(cur ^ 1, kbase + 64);
            cp_wait<1>();
        } else {
            cp_wait<0>();
        }
        __syncthreads();

        const uint32_t* sK = fsm + (cur * 2 + 0) * AWORDS;
        const uint32_t* sV = fsm + (cur * 2 + 1) * AWORDS;

        // ---- QK^T: S[16 x 64] per warp (B pairs via LDS.64)
        float S[8][4];
#pragma unroll
        for (int nt = 0; nt < 8; ++nt) {
            float c[4] = {0.f, 0.f, 0.f, 0.f};
            const uint32_t* r = &sK[(8 * nt + gID) * KP2];
#pragma unroll
            for (int ks = 0; ks < 4; ++ks) {
                const uint2 w0 = *(const uint2*)&r[2 * (8 * ks + tig)];
                const uint2 w1 = *(const uint2*)&r[2 * (8 * ks + 4 + tig)];
                mma_bf16(c, qhi[ks], w0.x, w1.x);
                mma_bf16(c, qhi[ks], w0.y, w1.y);
                mma_bf16(c, qlo[ks], w0.x, w1.x);
            }
            S[nt][0] = c[0]; S[nt][1] = c[1]; S[nt][2] = c[2]; S[nt][3] = c[3];
        }

        // ---- causal mask on the diagonal tile
        if (kt == bx) {
#pragma unroll
            for (int nt = 0; nt < 8; ++nt) {
                const int col = kbase + 8 * nt + 2 * tig;
                if (col     > rA) S[nt][0] = -1e30f;
                if (col + 1 > rA) S[nt][1] = -1e30f;
                if (col     > rB) S[nt][2] = -1e30f;
                if (col + 1 > rB) S[nt][3] = -1e30f;
            }
        }

        // ---- online softmax (log2 domain); l kept thread-partial
        float tmA = -1e30f, tmB = -1e30f;
#pragma unroll
        for (int nt = 0; nt < 8; ++nt) {
            tmA = fmaxf(tmA, fmaxf(S[nt][0], S[nt][1]));
            tmB = fmaxf(tmB, fmaxf(S[nt][2], S[nt][3]));
        }
        tmA = fmaxf(tmA, __shfl_xor_sync(0xffffffffu, tmA, 1));
        tmA = fmaxf(tmA, __shfl_xor_sync(0xffffffffu, tmA, 2));
        tmB = fmaxf(tmB, __shfl_xor_sync(0xffffffffu, tmB, 1));
        tmB = fmaxf(tmB, __shfl_xor_sync(0xffffffffu, tmB, 2));

        const float nmA = fmaxf(mA, tmA);
        const float nmB = fmaxf(mB, tmB);
        const float corrA = fast_exp2(mA - nmA);
        const float corrB = fast_exp2(mB - nmB);
        mA = nmA; mB = nmB;
        lA *= corrA; lB *= corrB;
#pragma unroll
        for (int nt = 0; nt < 8; ++nt) {
            O[nt][0] *= corrA; O[nt][1] *= corrA;
            O[nt][2] *= corrB; O[nt][3] *= corrB;
        }

        uint32_t ph[8][2], pl[8][2];
#pragma unroll
        for (int nt = 0; nt < 8; ++nt) {
            const float p0 = fast_exp2(S[nt][0] - nmA);
            const float p1 = fast_exp2(S[nt][1] - nmA);
            const float p2 = fast_exp2(S[nt][2] - nmB);
            const float p3 = fast_exp2(S[nt][3] - nmB);
            lA += p0 + p1; lB += p2 + p3;
            uint32_t h;
            h = pack_bf16x2(p0, p1); ph[nt][0] = h;
            pl[nt][0] = pack_bf16x2(p0 - bf16lo_f(h), p1 - bf16hi_f(h));
            h = pack_bf16x2(p2, p3); ph[nt][1] = h;
            pl[nt][1] = pack_bf16x2(p2 - bf16lo_f(h), p3 - bf16hi_f(h));
        }

        // ---- PV: O += P @ V (B pairs via LDS.64)
#pragma unroll
        for (int dnt = 0; dnt < 8; ++dnt) {
            const uint32_t* r = &sV[(8 * dnt + gID) * KP2];
#pragma unroll
            for (int ks = 0; ks < 4; ++ks) {
                uint32_t ah[4] = {ph[2 * ks][0], ph[2 * ks][1],
                                  ph[2 * ks + 1][0], ph[2 * ks + 1][1]};
                uint32_t al[4] = {pl[2 * ks][0], pl[2 * ks][1],
                                  pl[2 * ks + 1][0], pl[2 * ks + 1][1]};
                const uint2 w0 = *(const uint2*)&r[2 * (8 * ks + tig)];
                const uint2 w1 = *(const uint2*)&r[2 * (8 * ks + 4 + tig)];
                mma_bf16(O[dnt], ah, w0.x, w1.x);
                mma_bf16(O[dnt], ah, w0.y, w1.y);
                mma_bf16(O[dnt], al, w0.x, w1.x);
            }
        }
    }

    // ---- epilogue: reduce l across quad, normalize, tf32-round, store
    lA += __shfl_xor_sync(0xffffffffu, lA, 1);
    lA += __shfl_xor_sync(0xffffffffu, lA, 2);
    lB += __shfl_xor_sync(0xffffffffu, lB, 1);
    lB += __shfl_xor_sync(0xffffffffu, lB, 2);

    const float invA = 1.0f / lA;
    const float invB = 1.0f / lB;
    const int b = bh >> 4;
    const int h = bh & 15;
    float* oA = att + ((size_t)(b * TSEQ + rA)) * CDIM + h * DH;
    float* oB = att + ((size_t)(b * TSEQ + rB)) * CDIM + h * DH;
#pragma unroll
    for (int nt = 0; nt < 8; ++nt) {
        const int col = 8 * nt + 2 * tig;
        float2 vA, vB;
        vA.x = to_tf32(O[nt][0] * invA); vA.y = to_tf32(O[nt][1] * invA);
        vB.x = to_tf32(O[nt][2] * invB); vB.y = to_tf32(O[nt][3] * invB);
        *(float2*)(oA + col) = vA;
        *(float2*)(oB + col) = vB;
    }
}

// ----------------------------------------------------------------------------
extern "C" void kernel_launch(void* const* d_in, const int* in_sizes, int n_in,
                              void* d_out, int out_size)
{
    const float* x  = (const float*)d_in[0];
    const float* Wq = (const float*)d_in[1];
    const float* bq = (const float*)d_in[2];
    const float* Wk = (const float*)d_in[3];
    const float* bk = (const float*)d_in[4];
    const float* Wv = (const float*)d_in[5];
    const float* bv = (const float*)d_in[6];
    const float* Wo = (const float*)d_in[7];
    const float* bo = (const float*)d_in[8];
    float* out = (float*)d_out;

    float *Qp, *Kp, *Vp, *Ap, *xc, *wc;
    cudaGetSymbolAddress((void**)&Qp, g_Q);
    cudaGetSymbolAddress((void**)&Kp, g_K);
    cudaGetSymbolAddress((void**)&Vp, g_V);
    cudaGetSymbolAddress((void**)&Ap, g_att);
    cudaGetSymbolAddress((void**)&xc, g_xc);
    cudaGetSymbolAddress((void**)&wc, g_Wc);
    float* Wqc = wc;
    float* Wkc = wc + (size_t)CDIM * CDIM;
    float* Wvc = wc + 2 * (size_t)CDIM * CDIM;
    float* Woc = wc + 3 * (size_t)CDIM * CDIM;

    cudaFuncSetAttribute(gemm_mma_kernel<1, 3>,
                         cudaFuncAttributeMaxDynamicSharedMemorySize, GEMM_SMEM);
    cudaFuncSetAttribute(gemm_mma_kernel<0, 1>,
                         cudaFuncAttributeMaxDynamicSharedMemorySize, GEMM_SMEM);
    cudaFuncSetAttribute(flash_attn_mma_kernel,
                         cudaFuncAttributeMaxDynamicSharedMemorySize, FLASH_SMEM);

    // tf32 pre-rounding of x and all weights
    dim3 cvt_grid((BSZ * TSEQ * CDIM / 4 + 255) / 256, 5);
    cvt_tf32_kernel<<<cvt_grid, 256>>>(x, Wq, Wk, Wv, Wo);

    // fused Q/K/V projections
    dim3 qkv_grid(CDIM / 128, (BSZ * TSEQ) / 128, 3);
    gemm_mma_kernel<1, 3><<<qkv_grid, 256, GEMM_SMEM>>>(
        xc, Wqc, Wkc, Wvc, bq, bk, bv, Qp, Kp, Vp);

    // bf16 hi/lo pack of Q (scaled), K (interleaved), V (transposed+interleaved)
    dim3 pack_grid(TSEQ / 64, BSZ * HN);
    pack_kernel<<<pack_grid, 256>>>();

    // tensor-core flash attention (double-buffered, LDS.64 fragments)
    dim3 attn_grid(TSEQ / 64, BSZ * HN);              // (32, 32)
    flash_attn_mma_kernel<<<attn_grid, 128, FLASH_SMEM>>>(Ap);

    // output projection
    dim3 o_grid(CDIM / 128, (BSZ * TSEQ) / 128, 1);
    gemm_mma_kernel<0, 1><<<o_grid, 256, GEMM_SMEM>>>(
        Ap, Woc, Woc, Woc, bo, bo, bo, out, out, out);
}

// round 15
// speedup vs baseline: 1.0251x; 1.0251x over previous
#include <cuda_runtime.h>
#include <math_constants.h>
#include <cstdint>

#define BSZ   2
#define TSEQ  2048
#define CDIM  1024
#define HN    16
#define DH    64

// Scratch (allocation-free rule: __device__ globals)
__device__ float g_Q[(size_t)BSZ*HN*TSEQ*DH];   // [B,H,T,D]
__device__ float g_K[(size_t)BSZ*HN*TSEQ*DH];
__device__ float g_V[(size_t)BSZ*HN*TSEQ*DH];
__device__ float g_att[(size_t)BSZ*TSEQ*CDIM];  // [B,T,C] (tf32-rounded)
__device__ float g_xc[(size_t)BSZ*TSEQ*CDIM];   // x pre-rounded to tf32
__device__ float g_Wc[4][(size_t)CDIM*CDIM];    // Wq,Wk,Wv,Wo pre-rounded

// packed bf16x2 hi/lo buffers (produced once per call by pack_kernel)
#define NWORD_QK ((size_t)BSZ*HN*TSEQ*(DH/2))
#define NWORD_V  ((size_t)BSZ*HN*DH*(TSEQ/2))
__device__ uint32_t g_Qh[NWORD_QK], g_Ql[NWORD_QK];   // [bh][t][d/2], qscale folded
__device__ uint32_t g_Kh[NWORD_QK], g_Kl[NWORD_QK];   // [bh][t][d/2]
__device__ uint32_t g_Vh[NWORD_V],  g_Vl[NWORD_V];    // [bh][d][t/2] (transposed)

// ---------------------------------------------------------------------------
// helpers
// ---------------------------------------------------------------------------
__device__ __forceinline__ uint32_t smem_u32(const void* p) {
    uint32_t a;
    asm("{ .reg .u64 t; cvta.to.shared.u64 t, %1; cvt.u32.u64 %0, t; }"
        : "=r"(a) : "l"(p));
    return a;
}

__device__ __forceinline__ float fast_exp2(float x) {
    float y;
    asm("ex2.approx.f32 %0, %1;" : "=f"(y) : "f"(x));
    return y;
}

__device__ __forceinline__ float to_tf32(float x) {
    float r;
    asm("cvt.rna.tf32.f32 %0, %1;" : "=f"(r) : "f"(x));
    return r;
}

__device__ __forceinline__ void cp_async16(uint32_t dst, const void* src) {
    asm volatile("cp.async.cg.shared.global [%0], [%1], 16;" :: "r"(dst), "l"(src));
}
__device__ __forceinline__ void cp_commit() {
    asm volatile("cp.async.commit_group;");
}
template <int N>
__device__ __forceinline__ void cp_wait() {
    asm volatile("cp.async.wait_group %0;" :: "n"(N));
}

// pack two f32 into bf16x2: low half <- lo, high half <- hi
__device__ __forceinline__ uint32_t pack_bf16x2(float lo, float hi) {
    uint32_t r;
    asm("cvt.rn.bf16x2.f32 %0, %1, %2;" : "=r"(r) : "f"(hi), "f"(lo));
    return r;
}
__device__ __forceinline__ float bf16lo_f(uint32_t w) { return __uint_as_float(w << 16); }
__device__ __forceinline__ float bf16hi_f(uint32_t w) { return __uint_as_float(w & 0xFFFF0000u); }

// tf32 mma.sync m16n8k8 (non-volatile: pure computation)
__device__ __forceinline__ void mma_tf32(float* d, const uint32_t* a, const uint32_t* b)
{
    asm("mma.sync.aligned.m16n8k8.row.col.f32.tf32.tf32.f32 "
        "{%0,%1,%2,%3}, {%4,%5,%6,%7}, {%8,%9}, {%0,%1,%2,%3};"
        : "+f"(d[0]), "+f"(d[1]), "+f"(d[2]), "+f"(d[3])
        : "r"(a[0]), "r"(a[1]), "r"(a[2]), "r"(a[3]),
          "r"(b[0]), "r"(b[1]));
}

// bf16 mma.sync m16n8k16 (non-volatile)
__device__ __forceinline__ void mma_bf16(float* d, const uint32_t* a, uint32_t b0, uint32_t b1)
{
    asm("mma.sync.aligned.m16n8k16.row.col.f32.bf16.bf16.f32 "
        "{%0,%1,%2,%3}, {%4,%5,%6,%7}, {%8,%9}, {%0,%1,%2,%3};"
        : "+f"(d[0]), "+f"(d[1]), "+f"(d[2]), "+f"(d[3])
        : "r"(a[0]), "r"(a[1]), "r"(a[2]), "r"(a[3]),
          "r"(b0), "r"(b1));
}

// ---------------------------------------------------------------------------
// tf32 pre-conversion pass: x + 4 weight matrices, RNA-rounded once per call.
// ---------------------------------------------------------------------------
__global__ __launch_bounds__(256)
void cvt_tf32_kernel(const float* __restrict__ x,
                     const float* __restrict__ Wq, const float* __restrict__ Wk,
                     const float* __restrict__ Wv, const float* __restrict__ Wo)
{
    const int y = blockIdx.y;
    const float* src;
    float* dst;
    int n4;
    if (y == 0)      { src = x;  dst = g_xc;    n4 = BSZ * TSEQ * CDIM / 4; }
    else if (y == 1) { src = Wq; dst = g_Wc[0]; n4 = CDIM * CDIM / 4; }
    else if (y == 2) { src = Wk; dst = g_Wc[1]; n4 = CDIM * CDIM / 4; }
    else if (y == 3) { src = Wv; dst = g_Wc[2]; n4 = CDIM * CDIM / 4; }
    else             { src = Wo; dst = g_Wc[3]; n4 = CDIM * CDIM / 4; }

    const int i = blockIdx.x * blockDim.x + threadIdx.x;
    if (i < n4) {
        float4 v = ((const float4*)src)[i];
        v.x = to_tf32(v.x); v.y = to_tf32(v.y);
        v.z = to_tf32(v.z); v.w = to_tf32(v.w);
        ((float4*)dst)[i] = v;
    }
}

// ---------------------------------------------------------------------------
// Pack pass: bf16 hi/lo split of Q (qscale folded), K, and transposed V.
// Grid (T/64, B*H), 256 threads. Runs after the QKV GEMM.
// ---------------------------------------------------------------------------
__global__ __launch_bounds__(256)
void pack_kernel()
{
    __shared__ float sv[64][68];   // V tile [t][d]

    const int bh = blockIdx.y;
    const int t0 = blockIdx.x * 64;
    const int tid = threadIdx.x;
    const float qscale = 0.125f * 1.4426950408889634f;   // 1/sqrt(D)*log2(e)

    // load V tile [t0..t0+63][0..63] (coalesced float4)
#pragma unroll
    for (int i = 0; i < 4; ++i) {
        const int idx = tid + i * 256;
        const int row = idx >> 4;
        const int c4  = (idx & 15) * 4;
        *(float4*)&sv[row][c4] =
            *(const float4*)&g_V[((size_t)bh * TSEQ + t0 + row) * DH + c4];
    }

    // Q and K: elementwise pair packing (no transpose)
#pragma unroll
    for (int i = 0; i < 8; ++i) {
        const int idx = tid + i * 256;        // (row, pair)
        const int row = idx >> 5;
        const int p   = idx & 31;
        const size_t src = ((size_t)bh * TSEQ + t0 + row) * DH + 2 * p;
        const size_t dst = ((size_t)bh * TSEQ + t0 + row) * (DH / 2) + p;

        float2 q = *(const float2*)&g_Q[src];
        q.x *= qscale; q.y *= qscale;
        uint32_t qh = pack_bf16x2(q.x, q.y);
        g_Qh[dst] = qh;
        g_Ql[dst] = pack_bf16x2(q.x - bf16lo_f(qh), q.y - bf16hi_f(qh));

        float2 k = *(const float2*)&g_K[src];
        uint32_t kh = pack_bf16x2(k.x, k.y);
        g_Kh[dst] = kh;
        g_Kl[dst] = pack_bf16x2(k.x - bf16lo_f(kh), k.y - bf16hi_f(kh));
    }
    __syncthreads();

    // V transposed: word(d, p) = pack(V[t0+2p][d], V[t0+2p+1][d])
#pragma unroll
    for (int i = 0; i < 8; ++i) {
        const int idx = tid + i * 256;        // (d, pair)
        const int d = idx >> 5;
        const int p = idx & 31;
        const float v0 = sv[2 * p][d];
        const float v1 = sv[2 * p + 1][d];
        const uint32_t h = pack_bf16x2(v0, v1);
        const size_t dst = ((size_t)bh * DH + d) * (TSEQ / 2) + t0 / 2 + p;
        g_Vh[dst] = h;
        g_Vl[dst] = pack_bf16x2(v0 - bf16lo_f(h), v1 - bf16hi_f(h));
    }
}

// ---------------------------------------------------------------------------
// tf32 tensor-core GEMM-NT, 3-stage cp.async pipeline, 2 CTAs/SM:
//   out[M,N] = A[M,K] @ W[N,K]^T + bias,  M=4096, N=K=1024
// Depth-2 prefetch: chunks c+1 and c+2 in flight while chunk c computes.
// Smem: 3 buffers x (As+Bs) = 110.6 KB (x2 CTAs = 221 KB <= 228 carveout).
// ---------------------------------------------------------------------------
#define GPAD 36
#define GEMM_SMEM (6 * 128 * GPAD * 4)   // 3 buffers x (As + Bs) = 110592 B

template <int MODE, int NMAT>
__global__ __launch_bounds__(256, 2)
void gemm_mma_kernel(const float* __restrict__ A,
                     const float* __restrict__ W0, const float* __restrict__ W1,
                     const float* __restrict__ W2,
                     const float* __restrict__ b0, const float* __restrict__ b1,
                     const float* __restrict__ b2,
                     float* __restrict__ o0, float* __restrict__ o1,
                     float* __restrict__ o2)
{
    extern __shared__ float smem[];
    float (*As)[128][GPAD] = (float (*)[128][GPAD])(smem);
    float (*Bs)[128][GPAD] = (float (*)[128][GPAD])(smem + 3 * 128 * GPAD);
    const uint32_t smem_base = smem_u32(smem);

    const int z = (NMAT == 3) ? (int)blockIdx.z : 0;
    const float* __restrict__ W    = (z == 0) ? W0 : (z == 1 ? W1 : W2);
    const float* __restrict__ bias = (z == 0) ? b0 : (z == 1 ? b1 : b2);
    float* __restrict__ out        = (z == 0) ? o0 : (z == 1 ? o1 : o2);

    const int tid  = threadIdx.x;
    const int wid  = tid >> 5;
    const int lane = tid & 31;
    const int gID  = lane >> 2;
    const int tig  = lane & 3;
    const int n0 = blockIdx.x * 128;
    const int m0 = blockIdx.y * 128;
    const int wm = (wid >> 2) * 64;
    const int wn = (wid & 3) * 32;

    float acc[4][4][4];
#pragma unroll
    for (int mt = 0; mt < 4; ++mt)
#pragma unroll
        for (int nt = 0; nt < 4; ++nt)
#pragma unroll
            for (int r = 0; r < 4; ++r) acc[mt][nt][r] = 0.f;

    auto issue = [&](int buf, int k0) {
#pragma unroll
        for (int i = 0; i < 4; ++i) {
            const int idx = tid + i * 256;
            const int row = idx >> 3;
            const int q4  = (idx & 7) * 4;
            const uint32_t dA = smem_base +
                4u * (uint32_t)((buf * 128 + row) * GPAD + q4);
            const uint32_t dB = smem_base +
                4u * (uint32_t)(3 * 128 * GPAD + (buf * 128 + row) * GPAD + q4);
            cp_async16(dA, A + (size_t)(m0 + row) * CDIM + k0 + q4);
            cp_async16(dB, W + (size_t)(n0 + row) * CDIM + k0 + q4);
        }
        cp_commit();
    };

    issue(0, 0);
    issue(1, 32);

    for (int c = 0; c < 32; ++c) {
        const int cur = c % 3;
        if (c + 2 < 32) {
            issue((c + 2) % 3, (c + 2) * 32);   // keep 2 chunks in flight
            cp_wait<2>();                        // chunk c complete
        } else if (c + 1 < 32) {
            cp_wait<1>();
        } else {
            cp_wait<0>();
        }
        __syncthreads();

#pragma unroll
        for (int ks = 0; ks < 4; ++ks) {
            const int kk = ks * 8;
            uint32_t af[4][4];
#pragma unroll
            for (int mt = 0; mt < 4; ++mt) {
                const int r0 = wm + mt * 16 + gID;
                af[mt][0] = __float_as_uint(As[cur][r0    ][kk + tig    ]);
                af[mt][1] = __float_as_uint(As[cur][r0 + 8][kk + tig    ]);
                af[mt][2] = __float_as_uint(As[cur][r0    ][kk + tig + 4]);
                af[mt][3] = __float_as_uint(As[cur][r0 + 8][kk + tig + 4]);
            }
            uint32_t bf[4][2];
#pragma unroll
            for (int nt = 0; nt < 4; ++nt) {
                const int rn = wn + nt * 8 + gID;
                bf[nt][0] = __float_as_uint(Bs[cur][rn][kk + tig    ]);
                bf[nt][1] = __float_as_uint(Bs[cur][rn][kk + tig + 4]);
            }
#pragma unroll
            for (int mt = 0; mt < 4; ++mt)
#pragma unroll
                for (int nt = 0; nt < 4; ++nt)
                    mma_tf32(acc[mt][nt], af[mt], bf[nt]);
        }
        __syncthreads();      // all warps done with buf cur before its refill
    }

#pragma unroll
    for (int mt = 0; mt < 4; ++mt) {
#pragma unroll
        for (int nt = 0; nt < 4; ++nt) {
            const int mrow0 = m0 + wm + mt * 16 + gID;
            const int mrow1 = mrow0 + 8;
            const int ncol  = n0 + wn + nt * 8 + 2 * tig;
            const float bx = bias[ncol], by = bias[ncol + 1];
            float2 v0, v1;
            v0.x = acc[mt][nt][0] + bx; v0.y = acc[mt][nt][1] + by;
            v1.x = acc[mt][nt][2] + bx; v1.y = acc[mt][nt][3] + by;
            if (MODE == 0) {
                *(float2*)&out[(size_t)mrow0 * CDIM + ncol] = v0;
                *(float2*)&out[(size_t)mrow1 * CDIM + ncol] = v1;
            } else {
                const int h  = ncol >> 6;
                const int dd = ncol & 63;
                const int b0r = mrow0 >> 11, t0r = mrow0 & (TSEQ - 1);
                const int b1r = mrow1 >> 11, t1r = mrow1 & (TSEQ - 1);
                *(float2*)&out[(((size_t)(b0r * HN + h)) * TSEQ + t0r) * DH + dd] = v0;
                *(float2*)&out[(((size_t)(b1r * HN + h)) * TSEQ + t1r) * DH + dd] = v1;
            }
        }
    }
}

// ----------------------------------------------------------------------------
// Tensor-core causal flash attention (bf16 split-3, ~fp32 accurate).
// EXACT R12 body (measured 201.5 us): pre-packed K/V/Q, double-buffered
// cp.async staging, separate hi/lo smem arrays, in-loop l reduction.
// Block: 128 threads (4 warps). Q-tile 64, KV-tile 64. Grid: (T/64, B*H).
// ----------------------------------------------------------------------------
#define KPAD 36
#define TILE_WORDS (64 * KPAD)                      // 2304 words per array
#define FLASH_SMEM (2 * 4 * TILE_WORDS * 4)         // 73728 B

__global__ __launch_bounds__(128)
void flash_attn_mma_kernel(float* __restrict__ att)
{
    extern __shared__ uint32_t fsm[];
    // layout: [buf][Khi,Klo,Vhi,Vlo][TILE_WORDS]
    const uint32_t fsm_base = smem_u32(fsm);

    const int bh  = blockIdx.y;
    const int bx  = gridDim.x - 1 - blockIdx.x;
    const int q0  = bx * 64;
    const int tid = threadIdx.x;
    const int wid = tid >> 5;
    const int lane = tid & 31;
    const int gID = lane >> 2;
    const int tig = lane & 3;

    const int rA = q0 + wid * 16 + gID;
    const int rB = rA + 8;

    // ---- Q fragments from packed buffers (qscale already folded)
    uint32_t qhi[4][4], qlo[4][4];
    {
        const uint32_t* QhA = g_Qh + ((size_t)bh * TSEQ + rA) * (DH / 2);
        const uint32_t* QhB = g_Qh + ((size_t)bh * TSEQ + rB) * (DH / 2);
        const uint32_t* QlA = g_Ql + ((size_t)bh * TSEQ + rA) * (DH / 2);
        const uint32_t* QlB = g_Ql + ((size_t)bh * TSEQ + rB) * (DH / 2);
#pragma unroll
        for (int ks = 0; ks < 4; ++ks) {
            const int p = 8 * ks + tig;
            qhi[ks][0] = QhA[p];     qhi[ks][1] = QhB[p];
            qhi[ks][2] = QhA[p + 4]; qhi[ks][3] = QhB[p + 4];
            qlo[ks][0] = QlA[p];     qlo[ks][1] = QlB[p];
            qlo[ks][2] = QlA[p + 4]; qlo[ks][3] = QlB[p + 4];
        }
    }

    auto stage = [&](int buf, int kbase) {
        const uint32_t base = fsm_base + 4u * (uint32_t)(buf * 4 * TILE_WORDS);
#pragma unroll
        for (int i = 0; i < 4; ++i) {
            const int idx = tid + i * 128;      // 0..511
            const int row = idx >> 3;           // 0..63 (key for K, d for V)
            const int c   = idx & 7;            // 16B chunk within row
            const uint32_t off = 4u * (uint32_t)(row * KPAD + c * 4);
            const size_t srcK = ((size_t)bh * TSEQ + kbase + row) * (DH / 2) + c * 4;
            const size_t srcV = ((size_t)bh * DH + row) * (TSEQ / 2) + kbase / 2 + c * 4;
            cp_async16(base + 0 * 4 * TILE_WORDS + off, g_Kh + srcK);
            cp_async16(base + 1 * 4 * TILE_WORDS + off, g_Kl + srcK);
            cp_async16(base + 2 * 4 * TILE_WORDS + off, g_Vh + srcV);
            cp_async16(base + 3 * 4 * TILE_WORDS + off, g_Vl + srcV);
        }
        cp_commit();
    };

    float O[8][4];
#pragma unroll
    for (int nt = 0; nt < 8; ++nt)
#pragma unroll
        for (int r = 0; r < 4; ++r) O[nt][r] = 0.f;
    float mA = -1e30f, mB = -1e30f, lA = 0.f, lB = 0.f;

    const int ntiles = bx + 1;

    stage(0, 0);   // prologue: tile 0 into buffer 0

    for (int kt = 0; kt < ntiles; ++kt) {
        const int cur = kt & 1;
        const int kbase = kt * 64;

        __syncthreads();                  // all warps done with buffer cur (prev use)
        if (kt + 1 < ntiles) {
            stage(cur ^ 1, kbase + 64);   // prefetch next tile
            cp_wait<1>();                 // buffer cur complete
        } else {
            cp_wait<0>();
        }
        __syncthreads();                  // everyone's copies for cur visible

        const uint32_t* sKhi = fsm + (cur * 4 + 0) * TILE_WORDS;
        const uint32_t* sKlo = fsm + (cur * 4 + 1) * TILE_WORDS;
        const uint32_t* sVhi = fsm + (cur * 4 + 2) * TILE_WORDS;
        const uint32_t* sVlo = fsm + (cur * 4 + 3) * TILE_WORDS;

        // ---- QK^T: S[16 x 64] per warp
        float S[8][4];
#pragma unroll
        for (int nt = 0; nt < 8; ++nt) {
            float c[4] = {0.f, 0.f, 0.f, 0.f};
            const uint32_t* rh = &sKhi[(8 * nt + gID) * KPAD];
            const uint32_t* rl = &sKlo[(8 * nt + gID) * KPAD];
#pragma unroll
            for (int ks = 0; ks < 4; ++ks) {
                const uint32_t b0h = rh[8 * ks + tig];
                const uint32_t b1h = rh[8 * ks + 4 + tig];
                const uint32_t b0l = rl[8 * ks + tig];
                const uint32_t b1l = rl[8 * ks + 4 + tig];
                mma_bf16(c, qhi[ks], b0h, b1h);
                mma_bf16(c, qhi[ks], b0l, b1l);
                mma_bf16(c, qlo[ks], b0h, b1h);
            }
            S[nt][0] = c[0]; S[nt][1] = c[1]; S[nt][2] = c[2]; S[nt][3] = c[3];
        }

        // ---- causal mask on the diagonal tile
        if (kt == bx) {
#pragma unroll
            for (int nt = 0; nt < 8; ++nt) {
                const int col = kbase + 8 * nt + 2 * tig;
                if (col     > rA) S[nt][0] = -1e30f;
                if (col + 1 > rA) S[nt][1] = -1e30f;
                if (col     > rB) S[nt][2] = -1e30f;
                if (col + 1 > rB) S[nt][3] = -1e30f;
            }
        }

        // ---- online softmax (log2 domain)
        float tmA = -1e30f, tmB = -1e30f;
#pragma unroll
        for (int nt = 0; nt < 8; ++nt) {
            tmA = fmaxf(tmA, fmaxf(S[nt][0], S[nt][1]));
            tmB = fmaxf(tmB, fmaxf(S[nt][2], S[nt][3]));
        }
        tmA = fmaxf(tmA, __shfl_xor_sync(0xffffffffu, tmA, 1));
        tmA = fmaxf(tmA, __shfl_xor_sync(0xffffffffu, tmA, 2));
        tmB = fmaxf(tmB, __shfl_xor_sync(0xffffffffu, tmB, 1));
        tmB = fmaxf(tmB, __shfl_xor_sync(0xffffffffu, tmB, 2));

        const float nmA = fmaxf(mA, tmA);
        const float nmB = fmaxf(mB, tmB);
        const float corrA = fast_exp2(mA - nmA);
        const float corrB = fast_exp2(mB - nmB);
        mA = nmA; mB = nmB;
        lA *= corrA; lB *= corrB;
#pragma unroll
        for (int nt = 0; nt < 8; ++nt) {
            O[nt][0] *= corrA; O[nt][1] *= corrA;
            O[nt][2] *= corrB; O[nt][3] *= corrB;
        }

        uint32_t ph[8][2], pl[8][2];
        float sA = 0.f, sB = 0.f;
#pragma unroll
        for (int nt = 0; nt < 8; ++nt) {
            const float p0 = fast_exp2(S[nt][0] - nmA);
            const float p1 = fast_exp2(S[nt][1] - nmA);
            const float p2 = fast_exp2(S[nt][2] - nmB);
            const float p3 = fast_exp2(S[nt][3] - nmB);
            sA += p0 + p1; sB += p2 + p3;
            uint32_t h;
            h = pack_bf16x2(p0, p1); ph[nt][0] = h;
            pl[nt][0] = pack_bf16x2(p0 - bf16lo_f(h), p1 - bf16hi_f(h));
            h = pack_bf16x2(p2, p3); ph[nt][1] = h;
            pl[nt][1] = pack_bf16x2(p2 - bf16lo_f(h), p3 - bf16hi_f(h));
        }
        sA += __shfl_xor_sync(0xffffffffu, sA, 1);
        sA += __shfl_xor_sync(0xffffffffu, sA, 2);
        sB += __shfl_xor_sync(0xffffffffu, sB, 1);
        sB += __shfl_xor_sync(0xffffffffu, sB, 2);
        lA += sA; lB += sB;

        // ---- PV: O += P @ V
#pragma unroll
        for (int dnt = 0; dnt < 8; ++dnt) {
            const uint32_t* rh = &sVhi[(8 * dnt + gID) * KPAD];
            const uint32_t* rl = &sVlo[(8 * dnt + gID) * KPAD];
#pragma unroll
            for (int ks = 0; ks < 4; ++ks) {
                uint32_t ah[4] = {ph[2 * ks][0], ph[2 * ks][1],
                                  ph[2 * ks + 1][0], ph[2 * ks + 1][1]};
                uint32_t al[4] = {pl[2 * ks][0], pl[2 * ks][1],
                                  pl[2 * ks + 1][0], pl[2 * ks + 1][1]};
                const uint32_t b0h = rh[8 * ks + tig];
                const uint32_t b1h = rh[8 * ks + 4 + tig];
                const uint32_t b0l = rl[8 * ks + tig];
                const uint32_t b1l = rl[8 * ks + 4 + tig];
                mma_bf16(O[dnt], ah, b0h, b1h);
                mma_bf16(O[dnt], ah, b0l, b1l);
                mma_bf16(O[dnt], al, b0h, b1h);
            }
        }
    }

    // ---- epilogue: normalize, tf32-round, store to [B,T,C]
    const float invA = 1.0f / lA;
    const float invB = 1.0f / lB;
    const int b = bh >> 4;
    const int h = bh & 15;
    float* oA = att + ((size_t)(b * TSEQ + rA)) * CDIM + h * DH;
    float* oB = att + ((size_t)(b * TSEQ + rB)) * CDIM + h * DH;
#pragma unroll
    for (int nt = 0; nt < 8; ++nt) {
        const int col = 8 * nt + 2 * tig;
        float2 vA, vB;
        vA.x = to_tf32(O[nt][0] * invA); vA.y = to_tf32(O[nt][1] * invA);
        vB.x = to_tf32(O[nt][2] * invB); vB.y = to_tf32(O[nt][3] * invB);
        *(float2*)(oA + col) = vA;
        *(float2*)(oB + col) = vB;
    }
}

// ----------------------------------------------------------------------------
extern "C" void kernel_launch(void* const* d_in, const int* in_sizes, int n_in,
                              void* d_out, int out_size)
{
    const float* x  = (const float*)d_in[0];
    const float* Wq = (const float*)d_in[1];
    const float* bq = (const float*)d_in[2];
    const float* Wk = (const float*)d_in[3];
    const float* bk = (const float*)d_in[4];
    const float* Wv = (const float*)d_in[5];
    const float* bv = (const float*)d_in[6];
    const float* Wo = (const float*)d_in[7];
    const float* bo = (const float*)d_in[8];
    float* out = (float*)d_out;

    float *Qp, *Kp, *Vp, *Ap, *xc, *wc;
    cudaGetSymbolAddress((void**)&Qp, g_Q);
    cudaGetSymbolAddress((void**)&Kp, g_K);
    cudaGetSymbolAddress((void**)&Vp, g_V);
    cudaGetSymbolAddress((void**)&Ap, g_att);
    cudaGetSymbolAddress((void**)&xc, g_xc);
    cudaGetSymbolAddress((void**)&wc, g_Wc);
    float* Wqc = wc;
    float* Wkc = wc + (size_t)CDIM * CDIM;
    float* Wvc = wc + 2 * (size_t)CDIM * CDIM;
    float* Woc = wc + 3 * (size_t)CDIM * CDIM;

    cudaFuncSetAttribute(gemm_mma_kernel<1, 3>,
                         cudaFuncAttributeMaxDynamicSharedMemorySize, GEMM_SMEM);
    cudaFuncSetAttribute(gemm_mma_kernel<0, 1>,
                         cudaFuncAttributeMaxDynamicSharedMemorySize, GEMM_SMEM);
    cudaFuncSetAttribute(flash_attn_mma_kernel,
                         cudaFuncAttributeMaxDynamicSharedMemorySize, FLASH_SMEM);

    // tf32 pre-rounding of x and all weights
    dim3 cvt_grid((BSZ * TSEQ * CDIM / 4 + 255) / 256, 5);
    cvt_tf32_kernel<<<cvt_grid, 256>>>(x, Wq, Wk, Wv, Wo);

    // fused Q/K/V projections (3-stage pipeline)
    dim3 qkv_grid(CDIM / 128, (BSZ * TSEQ) / 128, 3);
    gemm_mma_kernel<1, 3><<<qkv_grid, 256, GEMM_SMEM>>>(
        xc, Wqc, Wkc, Wvc, bq, bk, bv, Qp, Kp, Vp);

    // bf16 hi/lo pack of Q (scaled), K, V (transposed)
    dim3 pack_grid(TSEQ / 64, BSZ * HN);
    pack_kernel<<<pack_grid, 256>>>();

    // tensor-core flash attention (R12 double-buffered body)
    dim3 attn_grid(TSEQ / 64, BSZ * HN);              // (32, 32)
    flash_attn_mma_kernel<<<attn_grid, 128, FLASH_SMEM>>>(Ap);

    // output projection (3-stage pipeline)
    dim3 o_grid(CDIM / 128, (BSZ * TSEQ) / 128, 1);
    gemm_mma_kernel<0, 1><<<o_grid, 256, GEMM_SMEM>>>(
        Ap, Woc, Woc, Woc, bo, bo, bo, out, out, out);
}

// round 16
// speedup vs baseline: 1.0727x; 1.0464x over previous
#include <cuda_runtime.h>
#include <math_constants.h>
#include <cstdint>

#define BSZ   2
#define TSEQ  2048
#define CDIM  1024
#define HN    16
#define DH    64

// Scratch (allocation-free rule: __device__ globals)
__device__ float g_V[(size_t)BSZ*HN*TSEQ*DH];   // [B,H,T,D] f32 (V only)
__device__ float g_att[(size_t)BSZ*TSEQ*CDIM];  // [B,T,C] (tf32-rounded)
__device__ float g_xc[(size_t)BSZ*TSEQ*CDIM];   // x pre-rounded to tf32
__device__ float g_Wc[4][(size_t)CDIM*CDIM];    // Wq,Wk,Wv,Wo pre-rounded

// packed bf16x2 hi/lo buffers
#define NWORD_QK ((size_t)BSZ*HN*TSEQ*(DH/2))
#define NWORD_V  ((size_t)BSZ*HN*DH*(TSEQ/2))
__device__ uint32_t g_Qh[NWORD_QK], g_Ql[NWORD_QK];   // [bh][t][d/2], qscale folded
__device__ uint32_t g_Kh[NWORD_QK], g_Kl[NWORD_QK];   // [bh][t][d/2]
__device__ uint32_t g_Vh[NWORD_V],  g_Vl[NWORD_V];    // [bh][d][t/2] (transposed)

#define QSCALE (0.125f * 1.4426950408889634f)   // 1/sqrt(D) * log2(e)

// ---------------------------------------------------------------------------
// helpers
// ---------------------------------------------------------------------------
__device__ __forceinline__ uint32_t smem_u32(const void* p) {
    uint32_t a;
    asm("{ .reg .u64 t; cvta.to.shared.u64 t, %1; cvt.u32.u64 %0, t; }"
        : "=r"(a) : "l"(p));
    return a;
}

__device__ __forceinline__ float fast_exp2(float x) {
    float y;
    asm("ex2.approx.f32 %0, %1;" : "=f"(y) : "f"(x));
    return y;
}

__device__ __forceinline__ float to_tf32(float x) {
    float r;
    asm("cvt.rna.tf32.f32 %0, %1;" : "=f"(r) : "f"(x));
    return r;
}

__device__ __forceinline__ void cp_async16(uint32_t dst, const void* src) {
    asm volatile("cp.async.cg.shared.global [%0], [%1], 16;" :: "r"(dst), "l"(src));
}
__device__ __forceinline__ void cp_commit() {
    asm volatile("cp.async.commit_group;");
}
template <int N>
__device__ __forceinline__ void cp_wait() {
    asm volatile("cp.async.wait_group %0;" :: "n"(N));
}

// pack two f32 into bf16x2: low half <- lo, high half <- hi
__device__ __forceinline__ uint32_t pack_bf16x2(float lo, float hi) {
    uint32_t r;
    asm("cvt.rn.bf16x2.f32 %0, %1, %2;" : "=r"(r) : "f"(hi), "f"(lo));
    return r;
}
__device__ __forceinline__ float bf16lo_f(uint32_t w) { return __uint_as_float(w << 16); }
__device__ __forceinline__ float bf16hi_f(uint32_t w) { return __uint_as_float(w & 0xFFFF0000u); }

// tf32 mma.sync m16n8k8 (non-volatile: pure computation)
__device__ __forceinline__ void mma_tf32(float* d, const uint32_t* a, const uint32_t* b)
{
    asm("mma.sync.aligned.m16n8k8.row.col.f32.tf32.tf32.f32 "
        "{%0,%1,%2,%3}, {%4,%5,%6,%7}, {%8,%9}, {%0,%1,%2,%3};"
        : "+f"(d[0]), "+f"(d[1]), "+f"(d[2]), "+f"(d[3])
        : "r"(a[0]), "r"(a[1]), "r"(a[2]), "r"(a[3]),
          "r"(b[0]), "r"(b[1]));
}

// bf16 mma.sync m16n8k16 (non-volatile)
__device__ __forceinline__ void mma_bf16(float* d, const uint32_t* a, uint32_t b0, uint32_t b1)
{
    asm("mma.sync.aligned.m16n8k16.row.col.f32.bf16.bf16.f32 "
        "{%0,%1,%2,%3}, {%4,%5,%6,%7}, {%8,%9}, {%0,%1,%2,%3};"
        : "+f"(d[0]), "+f"(d[1]), "+f"(d[2]), "+f"(d[3])
        : "r"(a[0]), "r"(a[1]), "r"(a[2]), "r"(a[3]),
          "r"(b0), "r"(b1));
}

// ---------------------------------------------------------------------------
// tf32 pre-conversion pass: x + 4 weight matrices, RNA-rounded once per call.
// ---------------------------------------------------------------------------
__global__ __launch_bounds__(256)
void cvt_tf32_kernel(const float* __restrict__ x,
                     const float* __restrict__ Wq, const float* __restrict__ Wk,
                     const float* __restrict__ Wv, const float* __restrict__ Wo)
{
    const int y = blockIdx.y;
    const float* src;
    float* dst;
    int n4;
    if (y == 0)      { src = x;  dst = g_xc;    n4 = BSZ * TSEQ * CDIM / 4; }
    else if (y == 1) { src = Wq; dst = g_Wc[0]; n4 = CDIM * CDIM / 4; }
    else if (y == 2) { src = Wk; dst = g_Wc[1]; n4 = CDIM * CDIM / 4; }
    else if (y == 3) { src = Wv; dst = g_Wc[2]; n4 = CDIM * CDIM / 4; }
    else             { src = Wo; dst = g_Wc[3]; n4 = CDIM * CDIM / 4; }

    const int i = blockIdx.x * blockDim.x + threadIdx.x;
    if (i < n4) {
        float4 v = ((const float4*)src)[i];
        v.x = to_tf32(v.x); v.y = to_tf32(v.y);
        v.z = to_tf32(v.z); v.w = to_tf32(v.w);
        ((float4*)dst)[i] = v;
    }
}

// ---------------------------------------------------------------------------
// V pack pass: transposed bf16 hi/lo split of V only (Q/K packed in-GEMM).
// Grid (T/64, B*H), 256 threads.
// ---------------------------------------------------------------------------
__global__ __launch_bounds__(256)
void pack_v_kernel()
{
    __shared__ float sv[64][68];   // V tile [t][d]

    const int bh = blockIdx.y;
    const int t0 = blockIdx.x * 64;
    const int tid = threadIdx.x;

    // load V tile [t0..t0+63][0..63] (coalesced float4)
#pragma unroll
    for (int i = 0; i < 4; ++i) {
        const int idx = tid + i * 256;
        const int row = idx >> 4;
        const int c4  = (idx & 15) * 4;
        *(float4*)&sv[row][c4] =
            *(const float4*)&g_V[((size_t)bh * TSEQ + t0 + row) * DH + c4];
    }
    __syncthreads();

    // V transposed: word(d, p) = pack(V[t0+2p][d], V[t0+2p+1][d])
#pragma unroll
    for (int i = 0; i < 8; ++i) {
        const int idx = tid + i * 256;        // (d, pair)
        const int d = idx >> 5;
        const int p = idx & 31;
        const float v0 = sv[2 * p][d];
        const float v1 = sv[2 * p + 1][d];
        const uint32_t h = pack_bf16x2(v0, v1);
        const size_t dst = ((size_t)bh * DH + d) * (TSEQ / 2) + t0 / 2 + p;
        g_Vh[dst] = h;
        g_Vl[dst] = pack_bf16x2(v0 - bf16lo_f(h), v1 - bf16hi_f(h));
    }
}

// ---------------------------------------------------------------------------
// tf32 tensor-core GEMM-NT, 2-stage cp.async pipeline, 2 CTAs/SM (proven R12).
//   out[M,N] = A[M,K] @ W[N,K]^T + bias,  M=4096, N=K=1024
// MODE 0: out row-major [M,N].
// MODE 1 (NMAT=3): z=0 -> Q packed bf16 hi/lo (qscale folded),
//                  z=1 -> K packed bf16 hi/lo, z=2 -> V f32 head-split.
// ---------------------------------------------------------------------------
#define GPAD 36
#define GEMM_SMEM (4 * 128 * GPAD * 4)   // 2 buffers x (As + Bs) = 73728 B

template <int MODE, int NMAT>
__global__ __launch_bounds__(256, 2)
void gemm_mma_kernel(const float* __restrict__ A,
                     const float* __restrict__ W0, const float* __restrict__ W1,
                     const float* __restrict__ W2,
                     const float* __restrict__ b0, const float* __restrict__ b1,
                     const float* __restrict__ b2,
                     float* __restrict__ o0, float* __restrict__ o1,
                     float* __restrict__ o2)
{
    extern __shared__ float smem[];
    float (*As)[128][GPAD] = (float (*)[128][GPAD])(smem);
    float (*Bs)[128][GPAD] = (float (*)[128][GPAD])(smem + 2 * 128 * GPAD);
    const uint32_t smem_base = smem_u32(smem);

    const int z = (NMAT == 3) ? (int)blockIdx.z : 0;
    const float* __restrict__ W    = (z == 0) ? W0 : (z == 1 ? W1 : W2);
    const float* __restrict__ bias = (z == 0) ? b0 : (z == 1 ? b1 : b2);
    float* __restrict__ out        = (z == 0) ? o0 : (z == 1 ? o1 : o2);

    const int tid  = threadIdx.x;
    const int wid  = tid >> 5;
    const int lane = tid & 31;
    const int gID  = lane >> 2;
    const int tig  = lane & 3;
    const int n0 = blockIdx.x * 128;
    const int m0 = blockIdx.y * 128;
    const int wm = (wid >> 2) * 64;
    const int wn = (wid & 3) * 32;

    float acc[4][4][4];
#pragma unroll
    for (int mt = 0; mt < 4; ++mt)
#pragma unroll
        for (int nt = 0; nt < 4; ++nt)
#pragma unroll
            for (int r = 0; r < 4; ++r) acc[mt][nt][r] = 0.f;

    auto issue = [&](int buf, int k0) {
#pragma unroll
        for (int i = 0; i < 4; ++i) {
            const int idx = tid + i * 256;
            const int row = idx >> 3;
            const int q4  = (idx & 7) * 4;
            const uint32_t dA = smem_base +
                4u * (uint32_t)((buf * 128 + row) * GPAD + q4);
            const uint32_t dB = smem_base +
                4u * (uint32_t)(2 * 128 * GPAD + (buf * 128 + row) * GPAD + q4);
            cp_async16(dA, A + (size_t)(m0 + row) * CDIM + k0 + q4);
            cp_async16(dB, W + (size_t)(n0 + row) * CDIM + k0 + q4);
        }
        cp_commit();
    };

    issue(0, 0);

    for (int c = 0; c < 32; ++c) {
        const int cur = c & 1;
        if (c + 1 < 32) {
            issue(cur ^ 1, (c + 1) * 32);
            cp_wait<1>();
        } else {
            cp_wait<0>();
        }
        __syncthreads();

#pragma unroll
        for (int ks = 0; ks < 4; ++ks) {
            const int kk = ks * 8;
            uint32_t af[4][4];
#pragma unroll
            for (int mt = 0; mt < 4; ++mt) {
                const int r0 = wm + mt * 16 + gID;
                af[mt][0] = __float_as_uint(As[cur][r0    ][kk + tig    ]);
                af[mt][1] = __float_as_uint(As[cur][r0 + 8][kk + tig    ]);
                af[mt][2] = __float_as_uint(As[cur][r0    ][kk + tig + 4]);
                af[mt][3] = __float_as_uint(As[cur][r0 + 8][kk + tig + 4]);
            }
            uint32_t bf[4][2];
#pragma unroll
            for (int nt = 0; nt < 4; ++nt) {
                const int rn = wn + nt * 8 + gID;
                bf[nt][0] = __float_as_uint(Bs[cur][rn][kk + tig    ]);
                bf[nt][1] = __float_as_uint(Bs[cur][rn][kk + tig + 4]);
            }
#pragma unroll
            for (int mt = 0; mt < 4; ++mt)
#pragma unroll
                for (int nt = 0; nt < 4; ++nt)
                    mma_tf32(acc[mt][nt], af[mt], bf[nt]);
        }
        __syncthreads();
    }

    // ---- epilogue
#pragma unroll
    for (int mt = 0; mt < 4; ++mt) {
#pragma unroll
        for (int nt = 0; nt < 4; ++nt) {
            const int mrow0 = m0 + wm + mt * 16 + gID;
            const int mrow1 = mrow0 + 8;
            const int ncol  = n0 + wn + nt * 8 + 2 * tig;
            const float bx = bias[ncol], by = bias[ncol + 1];
            float2 v0, v1;
            v0.x = acc[mt][nt][0] + bx; v0.y = acc[mt][nt][1] + by;
            v1.x = acc[mt][nt][2] + bx; v1.y = acc[mt][nt][3] + by;
            if (MODE == 0) {
                *(float2*)&out[(size_t)mrow0 * CDIM + ncol] = v0;
                *(float2*)&out[(size_t)mrow1 * CDIM + ncol] = v1;
            } else {
                const int h  = ncol >> 6;
                const int dd = ncol & 63;
                const int b0r = mrow0 >> 11, t0r = mrow0 & (TSEQ - 1);
                const int b1r = mrow1 >> 11, t1r = mrow1 & (TSEQ - 1);
                if (z == 2) {
                    // V: f32 head-split (pack_v_kernel transposes later)
                    *(float2*)&out[(((size_t)(b0r * HN + h)) * TSEQ + t0r) * DH + dd] = v0;
                    *(float2*)&out[(((size_t)(b1r * HN + h)) * TSEQ + t1r) * DH + dd] = v1;
                } else {
                    // Q/K: pack bf16 hi/lo in-register (same ops as old pack_kernel)
                    const size_t i0 = (((size_t)(b0r * HN + h)) * TSEQ + t0r) * (DH / 2) + (dd >> 1);
                    const size_t i1 = (((size_t)(b1r * HN + h)) * TSEQ + t1r) * (DH / 2) + (dd >> 1);
                    if (z == 0) {
                        float q0x = v0.x * QSCALE, q0y = v0.y * QSCALE;
                        float q1x = v1.x * QSCALE, q1y = v1.y * QSCALE;
                        uint32_t h0 = pack_bf16x2(q0x, q0y);
                        uint32_t h1 = pack_bf16x2(q1x, q1y);
                        g_Qh[i0] = h0;
                        g_Ql[i0] = pack_bf16x2(q0x - bf16lo_f(h0), q0y - bf16hi_f(h0));
                        g_Qh[i1] = h1;
                        g_Ql[i1] = pack_bf16x2(q1x - bf16lo_f(h1), q1y - bf16hi_f(h1));
                    } else {
                        uint32_t h0 = pack_bf16x2(v0.x, v0.y);
                        uint32_t h1 = pack_bf16x2(v1.x, v1.y);
                        g_Kh[i0] = h0;
                        g_Kl[i0] = pack_bf16x2(v0.x - bf16lo_f(h0), v0.y - bf16hi_f(h0));
                        g_Kh[i1] = h1;
                        g_Kl[i1] = pack_bf16x2(v1.x - bf16lo_f(h1), v1.y - bf16hi_f(h1));
                    }
                }
            }
        }
    }
}

// ----------------------------------------------------------------------------
// Tensor-core causal flash attention (bf16 split-3, ~fp32 accurate).
// EXACT R12 body; now __launch_bounds__(128, 3) => 3 CTAs/SM (12 warps).
// Pre-packed K/V/Q, double-buffered cp.async staging.
// Block: 128 threads (4 warps). Q-tile 64, KV-tile 64. Grid: (T/64, B*H).
// ----------------------------------------------------------------------------
#define KPAD 36
#define TILE_WORDS (64 * KPAD)                      // 2304 words per array
#define FLASH_SMEM (2 * 4 * TILE_WORDS * 4)         // 73728 B

__global__ __launch_bounds__(128, 3)
void flash_attn_mma_kernel(float* __restrict__ att)
{
    extern __shared__ uint32_t fsm[];
    // layout: [buf][Khi,Klo,Vhi,Vlo][TILE_WORDS]
    const uint32_t fsm_base = smem_u32(fsm);

    const int bh  = blockIdx.y;
    const int bx  = gridDim.x - 1 - blockIdx.x;
    const int q0  = bx * 64;
    const int tid = threadIdx.x;
    const int wid = tid >> 5;
    const int lane = tid & 31;
    const int gID = lane >> 2;
    const int tig = lane & 3;

    const int rA = q0 + wid * 16 + gID;
    const int rB = rA + 8;

    // ---- Q fragments from packed buffers (qscale already folded)
    uint32_t qhi[4][4], qlo[4][4];
    {
        const uint32_t* QhA = g_Qh + ((size_t)bh * TSEQ + rA) * (DH / 2);
        const uint32_t* QhB = g_Qh + ((size_t)bh * TSEQ + rB) * (DH / 2);
        const uint32_t* QlA = g_Ql + ((size_t)bh * TSEQ + rA) * (DH / 2);
        const uint32_t* QlB = g_Ql + ((size_t)bh * TSEQ + rB) * (DH / 2);
#pragma unroll
        for (int ks = 0; ks < 4; ++ks) {
            const int p = 8 * ks + tig;
            qhi[ks][0] = QhA[p];     qhi[ks][1] = QhB[p];
            qhi[ks][2] = QhA[p + 4]; qhi[ks][3] = QhB[p + 4];
            qlo[ks][0] = QlA[p];     qlo[ks][1] = QlB[p];
            qlo[ks][2] = QlA[p + 4]; qlo[ks][3] = QlB[p + 4];
        }
    }

    auto stage = [&](int buf, int kbase) {
        const uint32_t base = fsm_base + 4u * (uint32_t)(buf * 4 * TILE_WORDS);
#pragma unroll
        for (int i = 0; i < 4; ++i) {
            const int idx = tid + i * 128;      // 0..511
            const int row = idx >> 3;           // 0..63 (key for K, d for V)
            const int c   = idx & 7;            // 16B chunk within row
            const uint32_t off = 4u * (uint32_t)(row * KPAD + c * 4);
            const size_t srcK = ((size_t)bh * TSEQ + kbase + row) * (DH / 2) + c * 4;
            const size_t srcV = ((size_t)bh * DH + row) * (TSEQ / 2) + kbase / 2 + c * 4;
            cp_async16(base + 0 * 4 * TILE_WORDS + off, g_Kh + srcK);
            cp_async16(base + 1 * 4 * TILE_WORDS + off, g_Kl + srcK);
            cp_async16(base + 2 * 4 * TILE_WORDS + off, g_Vh + srcV);
            cp_async16(base + 3 * 4 * TILE_WORDS + off, g_Vl + srcV);
        }
        cp_commit();
    };

    float O[8][4];
#pragma unroll
    for (int nt = 0; nt < 8; ++nt)
#pragma unroll
        for (int r = 0; r < 4; ++r) O[nt][r] = 0.f;
    float mA = -1e30f, mB = -1e30f, lA = 0.f, lB = 0.f;

    const int ntiles = bx + 1;

    stage(0, 0);   // prologue: tile 0 into buffer 0

    for (int kt = 0; kt < ntiles; ++kt) {
        const int cur = kt & 1;
        const int kbase = kt * 64;

        __syncthreads();                  // all warps done with buffer cur (prev use)
        if (kt + 1 < ntiles) {
            stage(cur ^ 1, kbase + 64);   // prefetch next tile
            cp_wait<1>();                 // buffer cur complete
        } else {
            cp_wait<0>();
        }
        __syncthreads();                  // everyone's copies for cur visible

        const uint32_t* sKhi = fsm + (cur * 4 + 0) * TILE_WORDS;
        const uint32_t* sKlo = fsm + (cur * 4 + 1) * TILE_WORDS;
        const uint32_t* sVhi = fsm + (cur * 4 + 2) * TILE_WORDS;
        const uint32_t* sVlo = fsm + (cur * 4 + 3) * TILE_WORDS;

        // ---- QK^T: S[16 x 64] per warp
        float S[8][4];
#pragma unroll
        for (int nt = 0; nt < 8; ++nt) {
            float c[4] = {0.f, 0.f, 0.f, 0.f};
            const uint32_t* rh = &sKhi[(8 * nt + gID) * KPAD];
            const uint32_t* rl = &sKlo[(8 * nt + gID) * KPAD];
#pragma unroll
            for (int ks = 0; ks < 4; ++ks) {
                const uint32_t b0h = rh[8 * ks + tig];
                const uint32_t b1h = rh[8 * ks + 4 + tig];
                const uint32_t b0l = rl[8 * ks + tig];
                const uint32_t b1l = rl[8 * ks + 4 + tig];
                mma_bf16(c, qhi[ks], b0h, b1h);
                mma_bf16(c, qhi[ks], b0l, b1l);
                mma_bf16(c, qlo[ks], b0h, b1h);
            }
            S[nt][0] = c[0]; S[nt][1] = c[1]; S[nt][2] = c[2]; S[nt][3] = c[3];
        }

        // ---- causal mask on the diagonal tile
        if (kt == bx) {
#pragma unroll
            for (int nt = 0; nt < 8; ++nt) {
                const int col = kbase + 8 * nt + 2 * tig;
                if (col     > rA) S[nt][0] = -1e30f;
                if (col + 1 > rA) S[nt][1] = -1e30f;
                if (col     > rB) S[nt][2] = -1e30f;
                if (col + 1 > rB) S[nt][3] = -1e30f;
            }
        }

        // ---- online softmax (log2 domain)
        float tmA = -1e30f, tmB = -1e30f;
#pragma unroll
        for (int nt = 0; nt < 8; ++nt) {
            tmA = fmaxf(tmA, fmaxf(S[nt][0], S[nt][1]));
            tmB = fmaxf(tmB, fmaxf(S[nt][2], S[nt][3]));
        }
        tmA = fmaxf(tmA, __shfl_xor_sync(0xffffffffu, tmA, 1));
        tmA = fmaxf(tmA, __shfl_xor_sync(0xffffffffu, tmA, 2));
        tmB = fmaxf(tmB, __shfl_xor_sync(0xffffffffu, tmB, 1));
        tmB = fmaxf(tmB, __shfl_xor_sync(0xffffffffu, tmB, 2));

        const float nmA = fmaxf(mA, tmA);
        const float nmB = fmaxf(mB, tmB);
        const float corrA = fast_exp2(mA - nmA);
        const float corrB = fast_exp2(mB - nmB);
        mA = nmA; mB = nmB;
        lA *= corrA; lB *= corrB;
#pragma unroll
        for (int nt = 0; nt < 8; ++nt) {
            O[nt][0] *= corrA; O[nt][1] *= corrA;
            O[nt][2] *= corrB; O[nt][3] *= corrB;
        }

        uint32_t ph[8][2], pl[8][2];
        float sA = 0.f, sB = 0.f;
#pragma unroll
        for (int nt = 0; nt < 8; ++nt) {
            const float p0 = fast_exp2(S[nt][0] - nmA);
            const float p1 = fast_exp2(S[nt][1] - nmA);
            const float p2 = fast_exp2(S[nt][2] - nmB);
            const float p3 = fast_exp2(S[nt][3] - nmB);
            sA += p0 + p1; sB += p2 + p3;
            uint32_t h;
            h = pack_bf16x2(p0, p1); ph[nt][0] = h;
            pl[nt][0] = pack_bf16x2(p0 - bf16lo_f(h), p1 - bf16hi_f(h));
            h = pack_bf16x2(p2, p3); ph[nt][1] = h;
            pl[nt][1] = pack_bf16x2(p2 - bf16lo_f(h), p3 - bf16hi_f(h));
        }
        sA += __shfl_xor_sync(0xffffffffu, sA, 1);
        sA += __shfl_xor_sync(0xffffffffu, sA, 2);
        sB += __shfl_xor_sync(0xffffffffu, sB, 1);
        sB += __shfl_xor_sync(0xffffffffu, sB, 2);
        lA += sA; lB += sB;

        // ---- PV: O += P @ V
#pragma unroll
        for (int dnt = 0; dnt < 8; ++dnt) {
            const uint32_t* rh = &sVhi[(8 * dnt + gID) * KPAD];
            const uint32_t* rl = &sVlo[(8 * dnt + gID) * KPAD];
#pragma unroll
            for (int ks = 0; ks < 4; ++ks) {
                uint32_t ah[4] = {ph[2 * ks][0], ph[2 * ks][1],
                                  ph[2 * ks + 1][0], ph[2 * ks + 1][1]};
                uint32_t al[4] = {pl[2 * ks][0], pl[2 * ks][1],
                                  pl[2 * ks + 1][0], pl[2 * ks + 1][1]};
                const uint32_t b0h = rh[8 * ks + tig];
                const uint32_t b1h = rh[8 * ks + 4 + tig];
                const uint32_t b0l = rl[8 * ks + tig];
                const uint32_t b1l = rl[8 * ks + 4 + tig];
                mma_bf16(O[dnt], ah, b0h, b1h);
                mma_bf16(O[dnt], ah, b0l, b1l);
                mma_bf16(O[dnt], al, b0h, b1h);
            }
        }
    }

    // ---- epilogue: normalize, tf32-round, store to [B,T,C]
    const float invA = 1.0f / lA;
    const float invB = 1.0f / lB;
    const int b = bh >> 4;
    const int h = bh & 15;
    float* oA = att + ((size_t)(b * TSEQ + rA)) * CDIM + h * DH;
    float* oB = att + ((size_t)(b * TSEQ + rB)) * CDIM + h * DH;
#pragma unroll
    for (int nt = 0; nt < 8; ++nt) {
        const int col = 8 * nt + 2 * tig;
        float2 vA, vB;
        vA.x = to_tf32(O[nt][0] * invA); vA.y = to_tf32(O[nt][1] * invA);
        vB.x = to_tf32(O[nt][2] * invB); vB.y = to_tf32(O[nt][3] * invB);
        *(float2*)(oA + col) = vA;
        *(float2*)(oB + col) = vB;
    }
}

// ----------------------------------------------------------------------------
extern "C" void kernel_launch(void* const* d_in, const int* in_sizes, int n_in,
                              void* d_out, int out_size)
{
    const float* x  = (const float*)d_in[0];
    const float* Wq = (const float*)d_in[1];
    const float* bq = (const float*)d_in[2];
    const float* Wk = (const float*)d_in[3];
    const float* bk = (const float*)d_in[4];
    const float* Wv = (const float*)d_in[5];
    const float* bv = (const float*)d_in[6];
    const float* Wo = (const float*)d_in[7];
    const float* bo = (const float*)d_in[8];
    float* out = (float*)d_out;

    float *Vp, *Ap, *xc, *wc;
    cudaGetSymbolAddress((void**)&Vp, g_V);
    cudaGetSymbolAddress((void**)&Ap, g_att);
    cudaGetSymbolAddress((void**)&xc, g_xc);
    cudaGetSymbolAddress((void**)&wc, g_Wc);
    float* Wqc = wc;
    float* Wkc = wc + (size_t)CDIM * CDIM;
    float* Wvc = wc + 2 * (size_t)CDIM * CDIM;
    float* Woc = wc + 3 * (size_t)CDIM * CDIM;

    cudaFuncSetAttribute(gemm_mma_kernel<1, 3>,
                         cudaFuncAttributeMaxDynamicSharedMemorySize, GEMM_SMEM);
    cudaFuncSetAttribute(gemm_mma_kernel<0, 1>,
                         cudaFuncAttributeMaxDynamicSharedMemorySize, GEMM_SMEM);
    cudaFuncSetAttribute(flash_attn_mma_kernel,
                         cudaFuncAttributeMaxDynamicSharedMemorySize, FLASH_SMEM);

    // tf32 pre-rounding of x and all weights
    dim3 cvt_grid((BSZ * TSEQ * CDIM / 4 + 255) / 256, 5);
    cvt_tf32_kernel<<<cvt_grid, 256>>>(x, Wq, Wk, Wv, Wo);

    // fused Q/K/V projections; Q/K packed bf16 in-epilogue, V f32
    dim3 qkv_grid(CDIM / 128, (BSZ * TSEQ) / 128, 3);
    gemm_mma_kernel<1, 3><<<qkv_grid, 256, GEMM_SMEM>>>(
        xc, Wqc, Wkc, Wvc, bq, bk, bv, Vp, Vp, Vp);

    // V transpose + bf16 hi/lo pack
    dim3 pack_grid(TSEQ / 64, BSZ * HN);
    pack_v_kernel<<<pack_grid, 256>>>();

    // tensor-core flash attention (R12 body, 3 CTAs/SM)
    dim3 attn_grid(TSEQ / 64, BSZ * HN);              // (32, 32)
    flash_attn_mma_kernel<<<attn_grid, 128, FLASH_SMEM>>>(Ap);

    // output projection
    dim3 o_grid(CDIM / 128, (BSZ * TSEQ) / 128, 1);
    gemm_mma_kernel<0, 1><<<o_grid, 256, GEMM_SMEM>>>(
        Ap, Woc, Woc, Woc, bo, bo, bo, out, out, out);
}